// round 1
// baseline (speedup 1.0000x reference)
#include <cuda_runtime.h>
#include <cuda_bf16.h>
#include <stdint.h>

// ---------------------------------------------------------------------------
// GCN 2-layer: out = GCNConv(relu(GCNConv(x,W1,b1)), W2, b2)
// with self-loops (ew=1) and symmetric normalization.
// Strategy: build CSR by dst once (int atomics), atomic-free warp-per-row SpMM,
// dense GEMMs with packed f32x2 FMA.
// ---------------------------------------------------------------------------

#define N_MAX   100000
#define E_MAX   1700000
#define FIN1    128
#define HID     64
#define CLS     32
#define SCAN_B  1024

typedef unsigned long long u64;

// ---- scratch (device globals; no allocation allowed) ----
__device__ int   g_cnt[N_MAX];
__device__ int   g_rowptr[N_MAX + 1];
__device__ int   g_cursor[N_MAX];        // also reused as exclusive-scan temp
__device__ float g_deg[N_MAX];
__device__ float g_dinv[N_MAX];
__device__ int   g_bsums[256];
__device__ int   g_csr_src[E_MAX];
__device__ float g_csr_w[E_MAX];
__device__ float g_xw1[(size_t)N_MAX * HID];   // 25.6 MB
__device__ float g_h  [(size_t)N_MAX * HID];   // 25.6 MB
__device__ float g_xw2[(size_t)N_MAX * CLS];   // 12.8 MB
__device__ int   g_is64;

// ---- packed f32x2 helpers ----
__device__ __forceinline__ u64 ffma2(u64 a, u64 b, u64 c) {
    u64 d;
    asm("fma.rn.f32x2 %0, %1, %2, %3;" : "=l"(d) : "l"(a), "l"(b), "l"(c));
    return d;
}
__device__ __forceinline__ u64 pack2(float x, float y) {
    u64 d;
    asm("mov.b64 %0, {%1, %2};" : "=l"(d) : "r"(__float_as_uint(x)), "r"(__float_as_uint(y)));
    return d;
}

// ---- edge-index width detection (jax may have emitted int32 or int64) ----
__global__ void k_detect(const unsigned int* __restrict__ u, int E) {
    int n = E < 64 ? E : 64;
    int all0 = 1;
    for (int i = 0; i < n; i++)
        if (u[2 * i + 1] != 0u) all0 = 0;
    g_is64 = all0;   // int64 node ids < 2^31 -> high words all zero
}

__device__ __forceinline__ void load_edge(const void* ei, int e, int E, int is64,
                                          int& s, int& d) {
    if (is64) {
        const long long* p = (const long long*)ei;
        s = (int)p[e];
        d = (int)p[(size_t)E + e];
    } else {
        const int* p = (const int*)ei;
        s = p[e];
        d = p[(size_t)E + e];
    }
}

// ---- init: cnt = 0, deg = 1 (self-loop weight) ----
__global__ void k_init(int n) {
    int i = blockIdx.x * blockDim.x + threadIdx.x;
    if (i >= n) return;
    g_cnt[i] = 0;
    g_deg[i] = 1.0f;
}

// ---- pass 1: per-dst counts + weighted degree ----
__global__ void k_edge1(const void* __restrict__ ei, const float* __restrict__ ew, int E) {
    int e = blockIdx.x * blockDim.x + threadIdx.x;
    if (e >= E) return;
    int is64 = g_is64;
    int s, d;
    load_edge(ei, e, E, is64, s, d);
    (void)s;
    atomicAdd(&g_cnt[d], 1);
    atomicAdd(&g_deg[d], ew[e]);
}

__global__ void k_dinv(int n) {
    int i = blockIdx.x * blockDim.x + threadIdx.x;
    if (i >= n) return;
    float dg = g_deg[i];
    g_dinv[i] = dg > 0.f ? rsqrtf(dg) : 0.f;
}

// ---- exclusive scan of g_cnt into g_cursor (3 kernels) ----
__global__ void k_scan1(int n) {
    __shared__ int sm[SCAN_B];
    int t = threadIdx.x;
    int i = blockIdx.x * SCAN_B + t;
    int v = (i < n) ? g_cnt[i] : 0;
    sm[t] = v;
    __syncthreads();
    for (int off = 1; off < SCAN_B; off <<= 1) {
        int add = (t >= off) ? sm[t - off] : 0;
        __syncthreads();
        sm[t] += add;
        __syncthreads();
    }
    if (i < n) g_cursor[i] = sm[t] - v;   // exclusive
    if (t == SCAN_B - 1) g_bsums[blockIdx.x] = sm[SCAN_B - 1];
}

__global__ void k_scan2(int nb) {
    int acc = 0;
    for (int b = 0; b < nb; b++) {
        int t = g_bsums[b];
        g_bsums[b] = acc;
        acc += t;
    }
}

__global__ void k_scan3(int n) {
    int i = blockIdx.x * SCAN_B + threadIdx.x;
    if (i >= n) return;
    int v = g_cursor[i] + g_bsums[blockIdx.x];
    g_rowptr[i] = v;
    g_cursor[i] = v;
    if (i == n - 1) g_rowptr[n] = v + g_cnt[i];
}

// ---- pass 2: fill CSR with (src, norm) ----
__global__ void k_fill(const void* __restrict__ ei, const float* __restrict__ ew, int E) {
    int e = blockIdx.x * blockDim.x + threadIdx.x;
    if (e >= E) return;
    int is64 = g_is64;
    int s, d;
    load_edge(ei, e, E, is64, s, d);
    float norm = g_dinv[s] * ew[e] * g_dinv[d];
    int slot = atomicAdd(&g_cursor[d], 1);
    g_csr_src[slot] = s;
    g_csr_w[slot] = norm;
}

// ---- dense GEMM: Y[n, FOUT] = X[n, FIN] @ W[FIN, FOUT], packed f32x2 ----
template <int FIN, int FOUT>
__global__ void __launch_bounds__(128) k_gemm(const float* __restrict__ X,
                                              const float* __restrict__ W,
                                              float* __restrict__ Y, int nrows) {
    __shared__ __align__(16) float Ws[FIN * FOUT];
    for (int i = threadIdx.x; i < FIN * FOUT; i += 128) Ws[i] = W[i];
    __syncthreads();

    int row = blockIdx.x * 128 + threadIdx.x;
    if (row >= nrows) return;

    u64 acc[FOUT / 2];
#pragma unroll
    for (int j = 0; j < FOUT / 2; j++) acc[j] = 0ull;

    const float4* x4 = reinterpret_cast<const float4*>(X + (size_t)row * FIN);
    const ulonglong2* Wq = reinterpret_cast<const ulonglong2*>(Ws);

#pragma unroll 2
    for (int k4 = 0; k4 < FIN / 4; k4++) {
        float4 xv = x4[k4];
        float xs[4] = {xv.x, xv.y, xv.z, xv.w};
#pragma unroll
        for (int kk = 0; kk < 4; kk++) {
            u64 xp = pack2(xs[kk], xs[kk]);
            int kb = (k4 * 4 + kk) * (FOUT / 4);
#pragma unroll
            for (int j4 = 0; j4 < FOUT / 4; j4++) {
                ulonglong2 wv = Wq[kb + j4];
                acc[2 * j4]     = ffma2(xp, wv.x, acc[2 * j4]);
                acc[2 * j4 + 1] = ffma2(xp, wv.y, acc[2 * j4 + 1]);
            }
        }
    }
    u64* yo = reinterpret_cast<u64*>(Y + (size_t)row * FOUT);
#pragma unroll
    for (int j = 0; j < FOUT / 2; j++) yo[j] = acc[j];
}

// ---- atomic-free SpMM: OUT[i,:] = sum_nnz w * XW[src,:] + dinv[i]^2*XW[i,:] + b ----
template <int F, bool RELU>
__global__ void __launch_bounds__(256) k_spmm(const float* __restrict__ XW,
                                              const float* __restrict__ bias,
                                              float* __restrict__ OUT, int nrows) {
    int lane = threadIdx.x & 31;
    int row = blockIdx.x * (blockDim.x >> 5) + (threadIdx.x >> 5);
    if (row >= nrows) return;

    float dn = g_dinv[row];
    float sl = dn * dn;                       // self-loop norm (ew = 1)
    const float* xr = XW + (size_t)row * F;
    float acc0 = sl * xr[lane];
    float acc1 = (F == 64) ? sl * xr[lane + 32] : 0.f;

    int start = g_rowptr[row];
    int end = g_rowptr[row + 1];
    for (int e0 = start; e0 < end; e0 += 32) {
        int m = end - e0;
        if (m > 32) m = 32;
        int s = 0;
        float w = 0.f;
        if (lane < m) {
            s = g_csr_src[e0 + lane];
            w = g_csr_w[e0 + lane];
        }
#pragma unroll 4
        for (int t = 0; t < m; t++) {
            float wt = __shfl_sync(0xffffffffu, w, t);
            int st = __shfl_sync(0xffffffffu, s, t);
            const float* g = XW + (size_t)st * F;
            acc0 = fmaf(wt, g[lane], acc0);
            if (F == 64) acc1 = fmaf(wt, g[lane + 32], acc1);
        }
    }
    acc0 += bias[lane];
    if (RELU) acc0 = fmaxf(acc0, 0.f);
    OUT[(size_t)row * F + lane] = acc0;
    if (F == 64) {
        acc1 += bias[lane + 32];
        if (RELU) acc1 = fmaxf(acc1, 0.f);
        OUT[(size_t)row * F + lane + 32] = acc1;
    }
}

// ---------------------------------------------------------------------------
extern "C" void kernel_launch(void* const* d_in, const int* in_sizes, int n_in,
                              void* d_out, int out_size) {
    const float* x   = (const float*)d_in[0];
    const void*  ei  = d_in[1];
    const float* ew  = (const float*)d_in[2];
    const float* W1  = (const float*)d_in[3];
    const float* b1  = (const float*)d_in[4];
    const float* W2  = (const float*)d_in[5];
    const float* b2  = (const float*)d_in[6];
    float* out = (float*)d_out;

    int E = in_sizes[2];            // edge_weight element count
    int N = in_sizes[0] / FIN1;     // x is [N, 128]
    if (N > N_MAX) N = N_MAX;
    if (E > E_MAX) E = E_MAX;

    int gbN = (N + 255) / 256;
    int gbE = (E + 255) / 256;
    int nb  = (N + SCAN_B - 1) / SCAN_B;

    k_detect<<<1, 1>>>((const unsigned int*)ei, E);
    k_init<<<gbN, 256>>>(N);
    k_edge1<<<gbE, 256>>>(ei, ew, E);
    k_dinv<<<gbN, 256>>>(N);
    k_scan1<<<nb, SCAN_B>>>(N);
    k_scan2<<<1, 1>>>(nb);
    k_scan3<<<nb, SCAN_B>>>(N);
    k_fill<<<gbE, 256>>>(ei, ew, E);

    // layer 1: xw1 = x @ W1 ; h = relu(spmm(xw1) + b1)
    k_gemm<FIN1, HID><<<(N + 127) / 128, 128>>>(x, W1, g_xw1, N);
    {
        // warp per row, 8 warps per block
        int grid = (N + 7) / 8;
        k_spmm<HID, true><<<grid, 256>>>(g_xw1, b1, g_h, N);
    }

    // layer 2: xw2 = h @ W2 ; out = spmm(xw2) + b2
    k_gemm<HID, CLS><<<(N + 127) / 128, 128>>>(g_h, W2, g_xw2, N);
    {
        int grid = (N + 7) / 8;
        k_spmm<CLS, false><<<grid, 256>>>(g_xw2, b2, out, N);
    }
}

// round 2
// speedup vs baseline: 1.2361x; 1.2361x over previous
#include <cuda_runtime.h>
#include <stdint.h>

// ---------------------------------------------------------------------------
// 2-layer GCN. CSR build (packed u64 atomics) + shfl-free staged SpMM.
// Layer-2 dense GEMM fused into SpMM1 epilogue.
// ---------------------------------------------------------------------------

#define N_MAX   100000
#define E_MAX   1700000
#define FIN1    128
#define HID     64
#define CLS     32
#define SCAN_B  1024

typedef unsigned long long u64;
typedef unsigned int u32;

// ---- scratch (device globals; no allocation allowed) ----
__device__ u64   g_degcnt[N_MAX];          // (count<<42) | fixed24(sum ew)
__device__ int   g_cnt[N_MAX];
__device__ int   g_rowptr[N_MAX + 1];
__device__ int   g_cursor[N_MAX];
__device__ float g_dinv[N_MAX];
__device__ int   g_bsums[128];
__device__ u64   g_csr[E_MAX];             // (f32bits(norm)<<32) | src
__device__ float g_xw1[(size_t)N_MAX * HID];
__device__ float g_xw2[(size_t)N_MAX * CLS];
__device__ int   g_is64;

// ---- packed f32x2 helpers (GEMM) ----
__device__ __forceinline__ u64 ffma2(u64 a, u64 b, u64 c) {
    u64 d;
    asm("fma.rn.f32x2 %0, %1, %2, %3;" : "=l"(d) : "l"(a), "l"(b), "l"(c));
    return d;
}
__device__ __forceinline__ u64 pack2(float x, float y) {
    u64 d;
    asm("mov.b64 %0, {%1, %2};" : "=l"(d) : "r"(__float_as_uint(x)), "r"(__float_as_uint(y)));
    return d;
}

// ---- init: zero deg/cnt accumulator; detect int32 vs int64 edge_index ----
__global__ void k_init(const u32* __restrict__ u, int E, int n) {
    int i = blockIdx.x * blockDim.x + threadIdx.x;
    if (i < n) g_degcnt[i] = 0ull;
    if (blockIdx.x == 0 && threadIdx.x < 32) {
        int cnt = E < 64 ? E : 64;
        bool nz = false;
        for (int j = threadIdx.x; j < cnt; j += 32) nz |= (u[2 * j + 1] != 0u);
        u32 b = __ballot_sync(0xffffffffu, nz);
        if (threadIdx.x == 0) g_is64 = (b == 0u) ? 1 : 0;
    }
}

__device__ __forceinline__ int load_dst(const void* ei, int e, int E, int is64) {
    if (is64) return (int)((const long long*)ei)[(size_t)E + e];
    return ((const int*)ei)[(size_t)E + e];
}
__device__ __forceinline__ int load_src(const void* ei, int e, int is64) {
    if (is64) return (int)((const long long*)ei)[e];
    return ((const int*)ei)[e];
}

// ---- pass 1: one u64 atomic per edge: count + fixed-point weighted degree ----
__global__ void k_edge1(const void* __restrict__ ei, const float* __restrict__ ew, int E) {
    int e = blockIdx.x * blockDim.x + threadIdx.x;
    if (e >= E) return;
    int d = load_dst(ei, e, E, g_is64);
    u64 add = ((u64)1 << 42) | (u64)(u32)__float2uint_rn(ew[e] * 16777216.0f);
    atomicAdd(&g_degcnt[d], add);
}

// ---- scan pass 1 (+ dinv computation folded in) ----
__global__ void k_scan1(int n) {
    __shared__ int sm[SCAN_B];
    int t = threadIdx.x;
    int i = blockIdx.x * SCAN_B + t;
    int v = 0;
    if (i < n) {
        u64 pc = g_degcnt[i];
        v = (int)(pc >> 42);
        float deg = 1.0f + (float)(pc & (((u64)1 << 42) - 1)) * (1.0f / 16777216.0f);
        g_dinv[i] = rsqrtf(deg);   // deg >= 1 always (self-loop)
        g_cnt[i] = v;
    }
    sm[t] = v;
    __syncthreads();
    for (int off = 1; off < SCAN_B; off <<= 1) {
        int add = (t >= off) ? sm[t - off] : 0;
        __syncthreads();
        sm[t] += add;
        __syncthreads();
    }
    if (i < n) g_cursor[i] = sm[t] - v;     // exclusive within block
    if (t == SCAN_B - 1) g_bsums[blockIdx.x] = sm[t];
}

__global__ void k_scan2(int nb) {
    int acc = 0;
    for (int b = 0; b < nb; b++) {
        int t = g_bsums[b];
        g_bsums[b] = acc;
        acc += t;
    }
}

__global__ void k_scan3(int n) {
    int i = blockIdx.x * SCAN_B + threadIdx.x;
    if (i >= n) return;
    int v = g_cursor[i] + g_bsums[blockIdx.x];
    g_rowptr[i] = v;
    g_cursor[i] = v;
    if (i == n - 1) g_rowptr[n] = v + g_cnt[i];
}

// ---- pass 2: fill CSR with packed (norm, src) ----
__global__ void k_fill(const void* __restrict__ ei, const float* __restrict__ ew, int E) {
    int e = blockIdx.x * blockDim.x + threadIdx.x;
    if (e >= E) return;
    int is64 = g_is64;
    int s = load_src(ei, e, is64);
    int d = load_dst(ei, e, E, is64);
    float norm = g_dinv[s] * ew[e] * g_dinv[d];
    int slot = atomicAdd(&g_cursor[d], 1);
    g_csr[slot] = ((u64)__float_as_uint(norm) << 32) | (u32)s;
}

// ---- dense GEMM: Y[r,:] = X[r,:] @ W, thread-per-row, packed f32x2 ----
template <int FIN, int FOUT>
__global__ void __launch_bounds__(128) k_gemm(const float* __restrict__ X,
                                              const float* __restrict__ W,
                                              float* __restrict__ Y,
                                              int row0, int rowend) {
    __shared__ __align__(16) float Ws[FIN * FOUT];
    for (int i = threadIdx.x; i < FIN * FOUT; i += 128) Ws[i] = W[i];
    __syncthreads();

    int row = row0 + blockIdx.x * 128 + threadIdx.x;
    if (row >= rowend) return;

    u64 acc[FOUT / 2];
#pragma unroll
    for (int j = 0; j < FOUT / 2; j++) acc[j] = 0ull;

    const float4* x4 = reinterpret_cast<const float4*>(X + (size_t)row * FIN);
    const ulonglong2* Wq = reinterpret_cast<const ulonglong2*>(Ws);

#pragma unroll 2
    for (int k4 = 0; k4 < FIN / 4; k4++) {
        float4 xv = x4[k4];
        float xs[4] = {xv.x, xv.y, xv.z, xv.w};
#pragma unroll
        for (int kk = 0; kk < 4; kk++) {
            u64 xp = pack2(xs[kk], xs[kk]);
            int kb = (k4 * 4 + kk) * (FOUT / 4);
#pragma unroll
            for (int j4 = 0; j4 < FOUT / 4; j4++) {
                ulonglong2 wv = Wq[kb + j4];
                acc[2 * j4]     = ffma2(xp, wv.x, acc[2 * j4]);
                acc[2 * j4 + 1] = ffma2(xp, wv.y, acc[2 * j4 + 1]);
            }
        }
    }
    u64* yo = reinterpret_cast<u64*>(Y + (size_t)row * FOUT);
#pragma unroll
    for (int j = 0; j < FOUT / 2; j++) yo[j] = acc[j];
}

// ---- SpMM layer 1 (F=64) fused with h@W2 projection (writes xw2) ----
__global__ void __launch_bounds__(256) k_spmm1(const float* __restrict__ XW,
                                               const float* __restrict__ b1,
                                               const float* __restrict__ W2,
                                               float* __restrict__ XW2, int nrows) {
    __shared__ u64 ebuf[8][32];
    __shared__ float hrow[8][HID];
    __shared__ float W2s[HID * CLS];
    for (int i = threadIdx.x; i < HID * CLS; i += 256) W2s[i] = W2[i];
    __syncthreads();

    int wid = threadIdx.x >> 5, lane = threadIdx.x & 31;
    int row = blockIdx.x * 8 + wid;
    if (row >= nrows) return;

    float dn = g_dinv[row];
    float sl = dn * dn;
    const float* xr = XW + (size_t)row * HID;
    float a0 = sl * xr[lane];
    float a1 = sl * xr[lane + 32];

    int p = g_rowptr[row], pe = g_rowptr[row + 1];
    u64* buf = ebuf[wid];
    while (p < pe) {
        int m = pe - p;
        if (m > 32) m = 32;
        if (lane < m) buf[lane] = g_csr[p + lane];
        __syncwarp();
        int t = 0;
        for (; t + 4 <= m; t += 4) {
            u64 e0 = buf[t], e1 = buf[t + 1], e2 = buf[t + 2], e3 = buf[t + 3];
            const float* g0 = XW + (size_t)(u32)e0 * HID;
            const float* g1 = XW + (size_t)(u32)e1 * HID;
            const float* g2 = XW + (size_t)(u32)e2 * HID;
            const float* g3 = XW + (size_t)(u32)e3 * HID;
            float v00 = g0[lane], v01 = g0[lane + 32];
            float v10 = g1[lane], v11 = g1[lane + 32];
            float v20 = g2[lane], v21 = g2[lane + 32];
            float v30 = g3[lane], v31 = g3[lane + 32];
            float w0 = __uint_as_float((u32)(e0 >> 32));
            float w1 = __uint_as_float((u32)(e1 >> 32));
            float w2 = __uint_as_float((u32)(e2 >> 32));
            float w3 = __uint_as_float((u32)(e3 >> 32));
            a0 = fmaf(w0, v00, a0); a1 = fmaf(w0, v01, a1);
            a0 = fmaf(w1, v10, a0); a1 = fmaf(w1, v11, a1);
            a0 = fmaf(w2, v20, a0); a1 = fmaf(w2, v21, a1);
            a0 = fmaf(w3, v30, a0); a1 = fmaf(w3, v31, a1);
        }
        for (; t < m; t++) {
            u64 e0 = buf[t];
            const float* g0 = XW + (size_t)(u32)e0 * HID;
            float w0 = __uint_as_float((u32)(e0 >> 32));
            a0 = fmaf(w0, g0[lane], a0);
            a1 = fmaf(w0, g0[lane + 32], a1);
        }
        __syncwarp();
        p += 32;
    }
    // bias + relu -> h row in smem
    a0 = fmaxf(a0 + b1[lane], 0.0f);
    a1 = fmaxf(a1 + b1[lane + 32], 0.0f);
    hrow[wid][lane] = a0;
    hrow[wid][lane + 32] = a1;
    __syncwarp();
    // fused projection: xw2[row, lane] = sum_k h[k] * W2[k, lane]
    float acc = 0.0f;
#pragma unroll
    for (int k = 0; k < HID; k++)
        acc = fmaf(hrow[wid][k], W2s[k * CLS + lane], acc);
    XW2[(size_t)row * CLS + lane] = acc;
}

// ---- SpMM layer 2 (F=32), writes final output (+b2) ----
__global__ void __launch_bounds__(256) k_spmm2(const float* __restrict__ XW2,
                                               const float* __restrict__ b2,
                                               float* __restrict__ OUT, int nrows) {
    __shared__ u64 ebuf[8][32];
    int wid = threadIdx.x >> 5, lane = threadIdx.x & 31;
    int row = blockIdx.x * 8 + wid;
    if (row >= nrows) return;

    float dn = g_dinv[row];
    float sl = dn * dn;
    float a0 = sl * XW2[(size_t)row * CLS + lane];

    int p = g_rowptr[row], pe = g_rowptr[row + 1];
    u64* buf = ebuf[wid];
    while (p < pe) {
        int m = pe - p;
        if (m > 32) m = 32;
        if (lane < m) buf[lane] = g_csr[p + lane];
        __syncwarp();
        int t = 0;
        for (; t + 4 <= m; t += 4) {
            u64 e0 = buf[t], e1 = buf[t + 1], e2 = buf[t + 2], e3 = buf[t + 3];
            float v0 = XW2[(size_t)(u32)e0 * CLS + lane];
            float v1 = XW2[(size_t)(u32)e1 * CLS + lane];
            float v2 = XW2[(size_t)(u32)e2 * CLS + lane];
            float v3 = XW2[(size_t)(u32)e3 * CLS + lane];
            a0 = fmaf(__uint_as_float((u32)(e0 >> 32)), v0, a0);
            a0 = fmaf(__uint_as_float((u32)(e1 >> 32)), v1, a0);
            a0 = fmaf(__uint_as_float((u32)(e2 >> 32)), v2, a0);
            a0 = fmaf(__uint_as_float((u32)(e3 >> 32)), v3, a0);
        }
        for (; t < m; t++) {
            u64 e0 = buf[t];
            a0 = fmaf(__uint_as_float((u32)(e0 >> 32)),
                      XW2[(size_t)(u32)e0 * CLS + lane], a0);
        }
        __syncwarp();
        p += 32;
    }
    OUT[(size_t)row * CLS + lane] = a0 + b2[lane];
}

// ---------------------------------------------------------------------------
extern "C" void kernel_launch(void* const* d_in, const int* in_sizes, int n_in,
                              void* d_out, int out_size) {
    const float* x  = (const float*)d_in[0];
    const void*  ei = d_in[1];
    const float* ew = (const float*)d_in[2];
    const float* W1 = (const float*)d_in[3];
    const float* b1 = (const float*)d_in[4];
    const float* W2 = (const float*)d_in[5];
    const float* b2 = (const float*)d_in[6];
    float* out = (float*)d_out;

    int E = in_sizes[2];
    int N = in_sizes[0] / FIN1;
    if (N > N_MAX) N = N_MAX;
    if (E > E_MAX) E = E_MAX;

    int gbE = (E + 255) / 256;
    int nb  = (N + SCAN_B - 1) / SCAN_B;
    int Nh  = (N + 1) / 2;

    // launch order puts k_edge1 4th (the ncu -s 5 -c 1 slot from round 1)
    k_init<<<(N + 255) / 256, 256>>>((const u32*)ei, E, N);                 // 1
    k_gemm<FIN1, HID><<<(Nh + 127) / 128, 128>>>(x, W1, g_xw1, 0, Nh);     // 2
    k_gemm<FIN1, HID><<<(N - Nh + 127) / 128, 128>>>(x, W1, g_xw1, Nh, N); // 3
    k_edge1<<<gbE, 256>>>(ei, ew, E);                                      // 4 (profiled)
    k_scan1<<<nb, SCAN_B>>>(N);                                            // 5
    k_scan2<<<1, 1>>>(nb);                                                 // 6
    k_scan3<<<nb, SCAN_B>>>(N);                                            // 7
    k_fill<<<gbE, 256>>>(ei, ew, E);                                       // 8
    k_spmm1<<<(N + 7) / 8, 256>>>(g_xw1, b1, W2, g_xw2, N);                // 9
    k_spmm2<<<(N + 7) / 8, 256>>>(g_xw2, b2, out, N);                      // 10
}

// round 3
// speedup vs baseline: 18.5606x; 15.0153x over previous
#include <cuda_runtime.h>
#include <stdint.h>

// ---------------------------------------------------------------------------
// 2-layer GCN in ONE persistent kernel (software grid barriers).
// Theory: harness cost ~490us per launch dominates; minimize launches to 1.
// ---------------------------------------------------------------------------

#define N_MAXC  100000
#define E_MAXC  1700000
#define FIN1    128
#define HID     64
#define CLS     32
#define NB      256
#define BS      256
#define NT      (NB * BS)

typedef unsigned long long u64;
typedef unsigned int u32;

// ---- device scratch ----
__device__ u64   g_degcnt[N_MAXC];           // (count<<42) | fixed24(sum ew)
__device__ int   g_rowptr[N_MAXC + 1];
__device__ int   g_cursor[N_MAXC];
__device__ float g_dinv[N_MAXC];
__device__ int   g_bsums[NB];
__device__ u64   g_csr[E_MAXC];              // (f32bits(norm)<<32) | src
__device__ float g_xw1[(size_t)N_MAXC * HID];
__device__ float g_xw2[(size_t)N_MAXC * CLS];
__device__ int   g_count;                    // barrier arrive counter
__device__ int   g_gen;                      // barrier generation (monotonic)

// ---- packed f32x2 helpers ----
__device__ __forceinline__ u64 ffma2(u64 a, u64 b, u64 c) {
    u64 d;
    asm("fma.rn.f32x2 %0, %1, %2, %3;" : "=l"(d) : "l"(a), "l"(b), "l"(c));
    return d;
}
__device__ __forceinline__ u64 pack2(float x) {
    u64 d;
    asm("mov.b64 %0, {%1, %1};" : "=l"(d) : "r"(__float_as_uint(x)));
    return d;
}

// ---- grid barrier (generation-based; expect passed from tid0's base) ----
__device__ __forceinline__ void gbar(int expect) {
    __syncthreads();
    if (threadIdx.x == 0) {
        __threadfence();
        int t = atomicAdd(&g_count, 1);
        if (t == NB - 1) {
            g_count = 0;
            __threadfence();
            *(volatile int*)&g_gen = expect;
        } else {
            while (*(volatile int*)&g_gen - expect < 0) {}
            __threadfence();
        }
    }
    __syncthreads();
}

__global__ void __launch_bounds__(BS, 2) mega(
    const float* __restrict__ x, const void* __restrict__ ei,
    const float* __restrict__ ew, const float* __restrict__ W1,
    const float* __restrict__ b1, const float* __restrict__ W2,
    const float* __restrict__ b2, float* __restrict__ out,
    int N, int E)
{
    __shared__ __align__(16) float s_f[FIN1 * HID];   // 32KB: W1, later W2
    __shared__ int   s_scan[BS];
    __shared__ u64   s_ebuf[8][32];
    __shared__ float s_hrow[8][HID];
    __shared__ int   s_is64;

    const int tid = threadIdx.x;
    const int b   = blockIdx.x;
    const int gtid = b * BS + tid;

    int ebase = 0;
    if (tid == 0) ebase = *(volatile int*)&g_gen;   // before any arrive: stable

    // ---------------- phase A: zero degcnt + int32/int64 detection ----------
    for (int i = gtid; i < N; i += NT) g_degcnt[i] = 0ull;
    if (tid < 32) {
        const u32* u = (const u32*)ei;
        int cnt = E < 64 ? E : 64;
        bool nz = false;
        for (int j = tid; j < cnt; j += 32) nz |= (u[2 * j + 1] != 0u);
        u32 bl = __ballot_sync(0xffffffffu, nz);
        if (tid == 0) s_is64 = (bl == 0u) ? 1 : 0;   // high words all 0 => i64
    }
    gbar(ebase + 1);
    const int is64 = s_is64;

    // ---------------- phase B: edge degree atomics + dense GEMM1 ------------
    for (int i = tid; i < FIN1 * HID; i += BS) s_f[i] = W1[i];
    for (int e = gtid; e < E; e += NT) {
        int d = is64 ? (int)((const long long*)ei)[(size_t)E + e]
                     : ((const int*)ei)[(size_t)E + e];
        u64 add = (1ull << 42) | (u64)(u32)__float2uint_rn(ew[e] * 16777216.0f);
        atomicAdd(&g_degcnt[d], add);
    }
    __syncthreads();
    for (int row = gtid; row < N; row += NT) {
        const float4* x4 = (const float4*)(x + (size_t)row * FIN1);
#pragma unroll
        for (int jt = 0; jt < 2; jt++) {          // two 32-col tiles (reg cap)
            u64 acc[16];
#pragma unroll
            for (int j = 0; j < 16; j++) acc[j] = 0ull;
#pragma unroll 2
            for (int k4 = 0; k4 < FIN1 / 4; k4++) {
                float4 xv = x4[k4];
                float xs[4] = {xv.x, xv.y, xv.z, xv.w};
#pragma unroll
                for (int kk = 0; kk < 4; kk++) {
                    u64 xp = pack2(xs[kk]);
                    const ulonglong2* wr =
                        (const ulonglong2*)&s_f[(k4 * 4 + kk) * HID + jt * 32];
#pragma unroll
                    for (int j4 = 0; j4 < 8; j4++) {
                        ulonglong2 wv = wr[j4];
                        acc[2 * j4]     = ffma2(xp, wv.x, acc[2 * j4]);
                        acc[2 * j4 + 1] = ffma2(xp, wv.y, acc[2 * j4 + 1]);
                    }
                }
            }
            u64* yo = (u64*)(g_xw1 + (size_t)row * HID + jt * 32);
#pragma unroll
            for (int j = 0; j < 16; j++) yo[j] = acc[j];
        }
    }
    gbar(ebase + 2);

    // ---------------- phase C: dinv + per-block count scan ------------------
    const int CH = (N + NB - 1) / NB;            // rows per block
    const int rbase = b * CH;
    const int rend = (rbase + CH < N) ? (rbase + CH) : N;
    const int r0 = rbase + tid, r1 = rbase + BS + tid;
    int c0 = 0, c1 = 0;
    if (r0 < rend) {
        u64 pc = g_degcnt[r0];
        c0 = (int)(pc >> 42);
        g_dinv[r0] = rsqrtf(1.0f + (float)(pc & ((1ull << 42) - 1)) * (1.0f / 16777216.0f));
    }
    if (r1 < rend) {
        u64 pc = g_degcnt[r1];
        c1 = (int)(pc >> 42);
        g_dinv[r1] = rsqrtf(1.0f + (float)(pc & ((1ull << 42) - 1)) * (1.0f / 16777216.0f));
    }
    s_scan[tid] = c0;
    __syncthreads();
    for (int off = 1; off < BS; off <<= 1) {
        int a = (tid >= off) ? s_scan[tid - off] : 0;
        __syncthreads();
        s_scan[tid] += a;
        __syncthreads();
    }
    int e0 = s_scan[tid] - c0;
    int T0 = s_scan[BS - 1];
    __syncthreads();
    s_scan[tid] = c1;
    __syncthreads();
    for (int off = 1; off < BS; off <<= 1) {
        int a = (tid >= off) ? s_scan[tid - off] : 0;
        __syncthreads();
        s_scan[tid] += a;
        __syncthreads();
    }
    int e1 = s_scan[tid] - c1 + T0;
    int tot = T0 + s_scan[BS - 1];
    if (r0 < rend) g_rowptr[r0] = e0;
    if (r1 < rend) g_rowptr[r1] = e1;
    if (tid == 0) g_bsums[b] = tot;
    gbar(ebase + 3);

    // ---------------- phase D: scan of block sums (block 0) -----------------
    if (b == 0) {
        int v = g_bsums[tid];
        s_scan[tid] = v;
        __syncthreads();
        for (int off = 1; off < BS; off <<= 1) {
            int a = (tid >= off) ? s_scan[tid - off] : 0;
            __syncthreads();
            s_scan[tid] += a;
            __syncthreads();
        }
        g_bsums[tid] = s_scan[tid] - v;            // exclusive
    }
    gbar(ebase + 4);

    // ---------------- phase E: finalize rowptr + cursor ---------------------
    {
        int off = g_bsums[b];
        if (r0 < rend) { int v = g_rowptr[r0] + off; g_rowptr[r0] = v; g_cursor[r0] = v; }
        if (r1 < rend) { int v = g_rowptr[r1] + off; g_rowptr[r1] = v; g_cursor[r1] = v; }
        if (gtid == 0) g_rowptr[N] = E;
    }
    gbar(ebase + 5);

    // ---------------- phase F: fill CSR -------------------------------------
    for (int e = gtid; e < E; e += NT) {
        int s, d;
        if (is64) {
            const long long* p = (const long long*)ei;
            s = (int)p[e]; d = (int)p[(size_t)E + e];
        } else {
            const int* p = (const int*)ei;
            s = p[e]; d = p[(size_t)E + e];
        }
        float norm = g_dinv[s] * ew[e] * g_dinv[d];
        int slot = atomicAdd(&g_cursor[d], 1);
        g_csr[slot] = ((u64)__float_as_uint(norm) << 32) | (u32)s;
    }
    gbar(ebase + 6);

    // ---------------- phase G: SpMM1 (F=64) + fused h@W2 --------------------
    for (int i = tid; i < HID * CLS; i += BS) s_f[i] = W2[i];
    __syncthreads();
    const int wid = tid >> 5, lane = tid & 31;
    for (int row = b * 8 + wid; row < N; row += NB * 8) {
        float dn = g_dinv[row];
        float sl = dn * dn;
        const float* xr = g_xw1 + (size_t)row * HID;
        float a0 = sl * xr[lane];
        float a1 = sl * xr[lane + 32];
        int p = g_rowptr[row], pe = g_rowptr[row + 1];
        u64* buf = s_ebuf[wid];
        while (p < pe) {
            int m = pe - p; if (m > 32) m = 32;
            if (lane < m) buf[lane] = g_csr[p + lane];
            __syncwarp();
            int t = 0;
            for (; t + 4 <= m; t += 4) {
                u64 q0 = buf[t], q1 = buf[t + 1], q2 = buf[t + 2], q3 = buf[t + 3];
                const float* g0 = g_xw1 + (size_t)(u32)q0 * HID;
                const float* g1 = g_xw1 + (size_t)(u32)q1 * HID;
                const float* g2 = g_xw1 + (size_t)(u32)q2 * HID;
                const float* g3 = g_xw1 + (size_t)(u32)q3 * HID;
                float v00 = g0[lane], v01 = g0[lane + 32];
                float v10 = g1[lane], v11 = g1[lane + 32];
                float v20 = g2[lane], v21 = g2[lane + 32];
                float v30 = g3[lane], v31 = g3[lane + 32];
                float w0 = __uint_as_float((u32)(q0 >> 32));
                float w1 = __uint_as_float((u32)(q1 >> 32));
                float w2 = __uint_as_float((u32)(q2 >> 32));
                float w3 = __uint_as_float((u32)(q3 >> 32));
                a0 = fmaf(w0, v00, a0); a1 = fmaf(w0, v01, a1);
                a0 = fmaf(w1, v10, a0); a1 = fmaf(w1, v11, a1);
                a0 = fmaf(w2, v20, a0); a1 = fmaf(w2, v21, a1);
                a0 = fmaf(w3, v30, a0); a1 = fmaf(w3, v31, a1);
            }
            for (; t < m; t++) {
                u64 q0 = buf[t];
                const float* g0 = g_xw1 + (size_t)(u32)q0 * HID;
                float w0 = __uint_as_float((u32)(q0 >> 32));
                a0 = fmaf(w0, g0[lane], a0);
                a1 = fmaf(w0, g0[lane + 32], a1);
            }
            __syncwarp();
            p += 32;
        }
        a0 = fmaxf(a0 + b1[lane], 0.0f);
        a1 = fmaxf(a1 + b1[lane + 32], 0.0f);
        s_hrow[wid][lane] = a0;
        s_hrow[wid][lane + 32] = a1;
        __syncwarp();
        float acc = 0.0f;
#pragma unroll
        for (int k = 0; k < HID; k++)
            acc = fmaf(s_hrow[wid][k], s_f[k * CLS + lane], acc);
        g_xw2[(size_t)row * CLS + lane] = acc;
        __syncwarp();
    }
    gbar(ebase + 7);

    // ---------------- phase H: SpMM2 (F=32) -> out --------------------------
    for (int row = b * 8 + wid; row < N; row += NB * 8) {
        float dn = g_dinv[row];
        float sl = dn * dn;
        float a0 = sl * g_xw2[(size_t)row * CLS + lane];
        int p = g_rowptr[row], pe = g_rowptr[row + 1];
        u64* buf = s_ebuf[wid];
        while (p < pe) {
            int m = pe - p; if (m > 32) m = 32;
            if (lane < m) buf[lane] = g_csr[p + lane];
            __syncwarp();
            int t = 0;
            for (; t + 4 <= m; t += 4) {
                u64 q0 = buf[t], q1 = buf[t + 1], q2 = buf[t + 2], q3 = buf[t + 3];
                float v0 = g_xw2[(size_t)(u32)q0 * CLS + lane];
                float v1 = g_xw2[(size_t)(u32)q1 * CLS + lane];
                float v2 = g_xw2[(size_t)(u32)q2 * CLS + lane];
                float v3 = g_xw2[(size_t)(u32)q3 * CLS + lane];
                a0 = fmaf(__uint_as_float((u32)(q0 >> 32)), v0, a0);
                a0 = fmaf(__uint_as_float((u32)(q1 >> 32)), v1, a0);
                a0 = fmaf(__uint_as_float((u32)(q2 >> 32)), v2, a0);
                a0 = fmaf(__uint_as_float((u32)(q3 >> 32)), v3, a0);
            }
            for (; t < m; t++) {
                u64 q0 = buf[t];
                a0 = fmaf(__uint_as_float((u32)(q0 >> 32)),
                          g_xw2[(size_t)(u32)q0 * CLS + lane], a0);
            }
            __syncwarp();
            p += 32;
        }
        out[(size_t)row * CLS + lane] = a0 + b2[lane];
    }
}

// ---------------------------------------------------------------------------
extern "C" void kernel_launch(void* const* d_in, const int* in_sizes, int n_in,
                              void* d_out, int out_size) {
    const float* x  = (const float*)d_in[0];
    const void*  ei = d_in[1];
    const float* ew = (const float*)d_in[2];
    const float* W1 = (const float*)d_in[3];
    const float* b1 = (const float*)d_in[4];
    const float* W2 = (const float*)d_in[5];
    const float* b2 = (const float*)d_in[6];
    float* out = (float*)d_out;

    int E = in_sizes[2];
    int N = in_sizes[0] / FIN1;
    if (N > N_MAXC) N = N_MAXC;
    if (E > E_MAXC) E = E_MAXC;

    mega<<<NB, BS>>>(x, ei, ew, W1, b1, W2, b2, out, N, E);
}

// round 4
// speedup vs baseline: 21.1520x; 1.1396x over previous
#include <cuda_runtime.h>
#include <stdint.h>

// ---------------------------------------------------------------------------
// 2-layer GCN, single persistent kernel. Round 4: occupancy push.
// 512 blocks x 256 thr, __launch_bounds__(256,4) => <=64 regs, 4 blocks/SM.
// ---------------------------------------------------------------------------

#define N_MAXC  100000
#define E_MAXC  1700000
#define FIN1    128
#define HID     64
#define CLS     32
#define NB      512
#define BS      256
#define NT      (NB * BS)

typedef unsigned long long u64;
typedef unsigned int u32;

// ---- device scratch ----
__device__ u64   g_degcnt[N_MAXC];           // (count<<42) | fixed24(sum ew)
__device__ int   g_cnt2[N_MAXC];             // per-dst fill counter
__device__ int   g_rowptr[N_MAXC + 1];
__device__ float g_dinv[N_MAXC];
__device__ int   g_bsums[NB];
__device__ u64   g_csr[E_MAXC];              // (f32bits(norm)<<32) | src
__device__ float g_xw1[(size_t)N_MAXC * HID];
__device__ float g_xw2[(size_t)N_MAXC * CLS];
__device__ int   g_count;                    // barrier arrive counter
__device__ int   g_gen;                      // barrier generation (monotonic)

// ---- packed f32x2 helpers ----
__device__ __forceinline__ u64 ffma2(u64 a, u64 b, u64 c) {
    u64 d;
    asm("fma.rn.f32x2 %0, %1, %2, %3;" : "=l"(d) : "l"(a), "l"(b), "l"(c));
    return d;
}
__device__ __forceinline__ u64 pack2(float x) {
    u64 d;
    asm("mov.b64 %0, {%1, %1};" : "=l"(d) : "r"(__float_as_uint(x)));
    return d;
}

// ---- grid barrier (generation-based) ----
__device__ __forceinline__ void gbar(int expect) {
    __syncthreads();
    if (threadIdx.x == 0) {
        __threadfence();
        int t = atomicAdd(&g_count, 1);
        if (t == NB - 1) {
            g_count = 0;
            __threadfence();
            *(volatile int*)&g_gen = expect;
        } else {
            while (*(volatile int*)&g_gen - expect < 0) {}
            __threadfence();
        }
    }
    __syncthreads();
}

__global__ void __launch_bounds__(BS, 4) mega(
    const float* __restrict__ x, const void* __restrict__ ei,
    const float* __restrict__ ew, const float* __restrict__ W1,
    const float* __restrict__ b1, const float* __restrict__ W2,
    const float* __restrict__ b2, float* __restrict__ out,
    int N, int E)
{
    __shared__ __align__(16) float s_f[FIN1 * HID];   // 32KB: W1, later W2
    __shared__ int   s_scan[BS];
    __shared__ u64   s_ebuf[8][32];
    __shared__ float s_hrow[8][HID];
    __shared__ int   s_is64;

    const int tid = threadIdx.x;
    const int b   = blockIdx.x;
    const int gtid = b * BS + tid;

    int ebase = 0;
    if (tid == 0) ebase = *(volatile int*)&g_gen;   // stable before any arrive

    // ---------------- phase A: zero degcnt/cnt2 + i32/i64 detection ---------
    for (int i = gtid; i < N; i += NT) { g_degcnt[i] = 0ull; g_cnt2[i] = 0; }
    if (tid < 32) {
        const u32* u = (const u32*)ei;
        int cnt = E < 64 ? E : 64;
        bool nz = false;
        for (int j = tid; j < cnt; j += 32) nz |= (u[2 * j + 1] != 0u);
        u32 bl = __ballot_sync(0xffffffffu, nz);
        if (tid == 0) s_is64 = (bl == 0u) ? 1 : 0;
    }
    gbar(ebase + 1);
    const int is64 = s_is64;

    // ---------------- phase B: edge degree atomics + dense GEMM1 ------------
    for (int i = tid; i < FIN1 * HID; i += BS) s_f[i] = W1[i];
    for (int e = gtid; e < E; e += NT) {
        int d = is64 ? (int)((const long long*)ei)[(size_t)E + e]
                     : ((const int*)ei)[(size_t)E + e];
        u64 add = (1ull << 42) | (u64)(u32)__float2uint_rn(ew[e] * 16777216.0f);
        atomicAdd(&g_degcnt[d], add);
    }
    __syncthreads();
    for (int row = gtid; row < N; row += NT) {
        const float4* x4 = (const float4*)(x + (size_t)row * FIN1);
#pragma unroll 1
        for (int jt = 0; jt < 2; jt++) {          // two 32-col tiles: 32 acc regs
            u64 acc[16];
#pragma unroll
            for (int j = 0; j < 16; j++) acc[j] = 0ull;
#pragma unroll 2
            for (int k4 = 0; k4 < FIN1 / 4; k4++) {
                float4 xv = x4[k4];
                float xs[4] = {xv.x, xv.y, xv.z, xv.w};
#pragma unroll
                for (int kk = 0; kk < 4; kk++) {
                    u64 xp = pack2(xs[kk]);
                    const ulonglong2* wr =
                        (const ulonglong2*)&s_f[(k4 * 4 + kk) * HID + jt * 32];
#pragma unroll
                    for (int j4 = 0; j4 < 8; j4++) {
                        ulonglong2 wv = wr[j4];
                        acc[2 * j4]     = ffma2(xp, wv.x, acc[2 * j4]);
                        acc[2 * j4 + 1] = ffma2(xp, wv.y, acc[2 * j4 + 1]);
                    }
                }
            }
            u64* yo = (u64*)(g_xw1 + (size_t)row * HID + jt * 32);
#pragma unroll
            for (int j = 0; j < 16; j++) yo[j] = acc[j];
        }
    }
    gbar(ebase + 2);

    // ---------------- phase C: dinv + per-block count scan ------------------
    const int CH = (N + NB - 1) / NB;            // rows per block (<= BS here)
    const int rbase = b * CH;
    const int rend = (rbase + CH < N) ? (rbase + CH) : N;
    const int r0 = rbase + tid;
    int c0 = 0;
    if (r0 < rend) {
        u64 pc = g_degcnt[r0];
        c0 = (int)(pc >> 42);
        g_dinv[r0] = rsqrtf(1.0f + (float)(pc & ((1ull << 42) - 1)) * (1.0f / 16777216.0f));
    }
    s_scan[tid] = c0;
    __syncthreads();
    for (int off = 1; off < BS; off <<= 1) {
        int a = (tid >= off) ? s_scan[tid - off] : 0;
        __syncthreads();
        s_scan[tid] += a;
        __syncthreads();
    }
    int ex0 = s_scan[tid] - c0;                   // exclusive within block
    if (r0 < rend) g_rowptr[r0] = ex0;
    if (tid == BS - 1) g_bsums[b] = s_scan[BS - 1];
    gbar(ebase + 3);

    // ---------------- phase DE: per-block offset + finalize rowptr ----------
    {
        int v = 0;
        for (int j = tid; j < b; j += BS) v += g_bsums[j];
        __syncthreads();                          // s_scan reuse
        s_scan[tid] = v;
        __syncthreads();
        for (int off = BS / 2; off > 0; off >>= 1) {
            if (tid < off) s_scan[tid] += s_scan[tid + off];
            __syncthreads();
        }
        int off_b = s_scan[0];
        if (r0 < rend) g_rowptr[r0] += off_b;
        if (gtid == 0) g_rowptr[N] = E;
    }
    gbar(ebase + 4);

    // ---------------- phase F: fill CSR -------------------------------------
    for (int e = gtid; e < E; e += NT) {
        int s, d;
        if (is64) {
            const long long* p = (const long long*)ei;
            s = (int)p[e]; d = (int)p[(size_t)E + e];
        } else {
            const int* p = (const int*)ei;
            s = p[e]; d = p[(size_t)E + e];
        }
        float norm = g_dinv[s] * ew[e] * g_dinv[d];
        int slot = g_rowptr[d] + atomicAdd(&g_cnt2[d], 1);
        g_csr[slot] = ((u64)__float_as_uint(norm) << 32) | (u32)s;
    }
    gbar(ebase + 5);

    // ---------------- phase G: SpMM1 (F=64) + fused h@W2 --------------------
    for (int i = tid; i < HID * CLS; i += BS) s_f[i] = W2[i];
    __syncthreads();
    const int wid = tid >> 5, lane = tid & 31;
    for (int row = b * 8 + wid; row < N; row += NB * 8) {
        float dn = g_dinv[row];
        float sl = dn * dn;
        const float* xr = g_xw1 + (size_t)row * HID;
        float a0 = sl * xr[lane];
        float a1 = sl * xr[lane + 32];
        int p = g_rowptr[row], pe = g_rowptr[row + 1];
        u64* buf = s_ebuf[wid];
        while (p < pe) {
            int m = pe - p; if (m > 32) m = 32;
            if (lane < m) buf[lane] = g_csr[p + lane];
            __syncwarp();
            int t = 0;
            for (; t + 4 <= m; t += 4) {
                u64 q0 = buf[t], q1 = buf[t + 1], q2 = buf[t + 2], q3 = buf[t + 3];
                const float* g0 = g_xw1 + (size_t)(u32)q0 * HID;
                const float* g1 = g_xw1 + (size_t)(u32)q1 * HID;
                const float* g2 = g_xw1 + (size_t)(u32)q2 * HID;
                const float* g3 = g_xw1 + (size_t)(u32)q3 * HID;
                float v00 = g0[lane], v01 = g0[lane + 32];
                float v10 = g1[lane], v11 = g1[lane + 32];
                float v20 = g2[lane], v21 = g2[lane + 32];
                float v30 = g3[lane], v31 = g3[lane + 32];
                float w0 = __uint_as_float((u32)(q0 >> 32));
                float w1 = __uint_as_float((u32)(q1 >> 32));
                float w2 = __uint_as_float((u32)(q2 >> 32));
                float w3 = __uint_as_float((u32)(q3 >> 32));
                a0 = fmaf(w0, v00, a0); a1 = fmaf(w0, v01, a1);
                a0 = fmaf(w1, v10, a0); a1 = fmaf(w1, v11, a1);
                a0 = fmaf(w2, v20, a0); a1 = fmaf(w2, v21, a1);
                a0 = fmaf(w3, v30, a0); a1 = fmaf(w3, v31, a1);
            }
            for (; t < m; t++) {
                u64 q0 = buf[t];
                const float* g0 = g_xw1 + (size_t)(u32)q0 * HID;
                float w0 = __uint_as_float((u32)(q0 >> 32));
                a0 = fmaf(w0, g0[lane], a0);
                a1 = fmaf(w0, g0[lane + 32], a1);
            }
            __syncwarp();
            p += 32;
        }
        a0 = fmaxf(a0 + b1[lane], 0.0f);
        a1 = fmaxf(a1 + b1[lane + 32], 0.0f);
        s_hrow[wid][lane] = a0;
        s_hrow[wid][lane + 32] = a1;
        __syncwarp();
        float acc = 0.0f;
#pragma unroll
        for (int k = 0; k < HID; k++)
            acc = fmaf(s_hrow[wid][k], s_f[k * CLS + lane], acc);
        g_xw2[(size_t)row * CLS + lane] = acc;
        __syncwarp();
    }
    gbar(ebase + 6);

    // ---------------- phase H: SpMM2 (F=32) -> out --------------------------
    for (int row = b * 8 + wid; row < N; row += NB * 8) {
        float dn = g_dinv[row];
        float sl = dn * dn;
        float a0 = sl * g_xw2[(size_t)row * CLS + lane];
        int p = g_rowptr[row], pe = g_rowptr[row + 1];
        u64* buf = s_ebuf[wid];
        while (p < pe) {
            int m = pe - p; if (m > 32) m = 32;
            if (lane < m) buf[lane] = g_csr[p + lane];
            __syncwarp();
            int t = 0;
            for (; t + 4 <= m; t += 4) {
                u64 q0 = buf[t], q1 = buf[t + 1], q2 = buf[t + 2], q3 = buf[t + 3];
                float v0 = g_xw2[(size_t)(u32)q0 * CLS + lane];
                float v1 = g_xw2[(size_t)(u32)q1 * CLS + lane];
                float v2 = g_xw2[(size_t)(u32)q2 * CLS + lane];
                float v3 = g_xw2[(size_t)(u32)q3 * CLS + lane];
                a0 = fmaf(__uint_as_float((u32)(q0 >> 32)), v0, a0);
                a0 = fmaf(__uint_as_float((u32)(q1 >> 32)), v1, a0);
                a0 = fmaf(__uint_as_float((u32)(q2 >> 32)), v2, a0);
                a0 = fmaf(__uint_as_float((u32)(q3 >> 32)), v3, a0);
            }
            for (; t < m; t++) {
                u64 q0 = buf[t];
                a0 = fmaf(__uint_as_float((u32)(q0 >> 32)),
                          g_xw2[(size_t)(u32)q0 * CLS + lane], a0);
            }
            __syncwarp();
            p += 32;
        }
        out[(size_t)row * CLS + lane] = a0 + b2[lane];
    }
}

// ---------------------------------------------------------------------------
extern "C" void kernel_launch(void* const* d_in, const int* in_sizes, int n_in,
                              void* d_out, int out_size) {
    const float* x  = (const float*)d_in[0];
    const void*  ei = d_in[1];
    const float* ew = (const float*)d_in[2];
    const float* W1 = (const float*)d_in[3];
    const float* b1 = (const float*)d_in[4];
    const float* W2 = (const float*)d_in[5];
    const float* b2 = (const float*)d_in[6];
    float* out = (float*)d_out;

    int E = in_sizes[2];
    int N = in_sizes[0] / FIN1;
    if (N > N_MAXC) N = N_MAXC;
    if (E > E_MAXC) E = E_MAXC;

    mega<<<NB, BS>>>(x, ei, ew, W1, b1, W2, b2, out, N, E);
}